// round 11
// baseline (speedup 1.0000x reference)
#include <cuda_runtime.h>
#include <cuda_fp16.h>
#include <cstdint>

#define NB 2
#define ND 8
#define NNODE 40
#define NH 128
#define HID 512
#define NJK (NNODE * NNODE)        // 1600
#define NJT 25                     // 1600/64 exact
#define TILE_M 64
#define TILE_N 256
#define NPASS (HID / TILE_N)       // 2
#define KCH 32
#define NCHUNKS (HID / KCH)        // 16
#define NSTG 3
#define THREADS 256

#define CST 36                     // C stage row stride (f32 words)
#define BSTW 20                    // B stage row stride (b32 words = 40 halfs)
#define AHB 80                     // A-half row stride (bytes)
#define AHBUF 5120                 // one A-half buffer (64*80)

// -------- device scratch --------
__device__ float  g_A[NB * NNODE * HID];   // hn        [b][i][k]
__device__ float  g_C[NB * NJK * HID];     // hp + b1   [b][jk][k]
__device__ __half g_W2h[HID * HID];        // W2^T      [n][k] half

// -------- dynamic smem layout (bytes) --------
#define SM_COFF   0                        // 64 ints
#define SM_SA     256                      // 512 f32
#define SM_BW     2304                     // 512 float2 (b2, W3)
#define SM_VRED   6400                     // 256 f32
#define SM_AH     7424                     // 2 x 5120 (double-buffered half tile)
#define SM_ST0    18432                    // stages, 1024-aligned
#define SM_BOFF   9216                     // B offset within stage (C = 64*144)
#define STG_SZ    29696                    // C 9216 + B 20480
#define SM_TOTAL  (SM_ST0 + NSTG * STG_SZ) // 107520  (x2 CTAs = 215040 <= 227KB)

__device__ __forceinline__ uint32_t smem_u32(const void* p) {
    uint32_t a;
    asm("{ .reg .u64 t; cvta.to.shared.u64 t, %1; cvt.u32.u64 %0, t; }" : "=r"(a) : "l"(p));
    return a;
}
__device__ __forceinline__ uint32_t h2pack(float lo, float hi) {
    uint32_t r;
    asm("cvt.rn.f16x2.f32 %0, %1, %2;" : "=r"(r) : "f"(hi), "f"(lo));
    return r;
}
__device__ __forceinline__ void cp16(uint32_t dst, const void* src) {
    asm volatile("cp.async.cg.shared.global [%0], [%1], 16;" :: "r"(dst), "l"(src) : "memory");
}
__device__ __forceinline__ void cp_commit() {
    asm volatile("cp.async.commit_group;" ::: "memory");
}
template <int N>
__device__ __forceinline__ void cp_waitg() {
    asm volatile("cp.async.wait_group %0;" :: "n"(N) : "memory");
}
__device__ __forceinline__ void ldmx4(uint32_t* r, uint32_t addr) {
    asm volatile("ldmatrix.sync.aligned.m8n8.x4.shared.b16 {%0,%1,%2,%3}, [%4];"
                 : "=r"(r[0]), "=r"(r[1]), "=r"(r[2]), "=r"(r[3]) : "r"(addr));
}
__device__ __forceinline__ void mma_f16(float* d, const uint32_t* a,
                                        uint32_t b0, uint32_t b1) {
    asm volatile(
        "mma.sync.aligned.m16n8k16.row.col.f32.f16.f16.f32 "
        "{%0,%1,%2,%3}, {%4,%5,%6,%7}, {%8,%9}, {%0,%1,%2,%3};"
        : "+f"(d[0]), "+f"(d[1]), "+f"(d[2]), "+f"(d[3])
        : "r"(a[0]), "r"(a[1]), "r"(a[2]), "r"(a[3]), "r"(b0), "r"(b1));
}

// ---------------------------------------------------------------------------
// Kernel A: nf = max_d(node_feature); g_A[b][i][:] = nf @ W1n
// ---------------------------------------------------------------------------
__global__ void k_node(const float* __restrict__ nfin,
                       const float* __restrict__ W1n) {
    __shared__ float s[NH];
    __shared__ float4 red[4][32];
    int bi = blockIdx.x, nq = blockIdx.y;
    int b = bi / NNODE, i = bi % NNODE;
    int t = threadIdx.x;

    const float* base = nfin + (((size_t)b * ND) * NNODE + i) * NH + t;
    float m = base[0];
#pragma unroll
    for (int d = 1; d < ND; d++)
        m = fmaxf(m, base[(size_t)d * NNODE * NH]);
    s[t] = m;
    __syncthreads();

    int hq = t >> 5, c = t & 31;
    int n = nq * 128 + c * 4;
    float a0 = 0.f, a1 = 0.f, a2 = 0.f, a3 = 0.f;
#pragma unroll 8
    for (int h = hq * 32; h < hq * 32 + 32; h++) {
        float4 wv = *(const float4*)(W1n + (size_t)h * HID + n);
        float x = s[h];
        a0 = fmaf(x, wv.x, a0);
        a1 = fmaf(x, wv.y, a1);
        a2 = fmaf(x, wv.z, a2);
        a3 = fmaf(x, wv.w, a3);
    }
    red[hq][c] = make_float4(a0, a1, a2, a3);
    __syncthreads();
    if (hq == 0) {
        float4 r0 = red[0][c], r1 = red[1][c], r2 = red[2][c], r3 = red[3][c];
        float4 o;
        o.x = r0.x + r1.x + r2.x + r3.x;
        o.y = r0.y + r1.y + r2.y + r3.y;
        o.z = r0.z + r1.z + r2.z + r3.z;
        o.w = r0.w + r1.w + r2.w + r3.w;
        *(float4*)(g_A + (size_t)bi * HID + n) = o;
    }
}

// ---------------------------------------------------------------------------
// Kernel B: pf = max_d(pairwise_feature); g_C[b][jk][:] = pf @ W1p + b1
// ---------------------------------------------------------------------------
__global__ void k_pair(const float* __restrict__ pfin,
                       const float* __restrict__ W1p,
                       const float* __restrict__ b1) {
    __shared__ float sP[8][NH];
    int row0 = blockIdx.x * 8;
    int b = row0 / NJK, jk0 = row0 % NJK;
    int t = threadIdx.x;

    for (int e = t; e < 8 * NH; e += 256) {
        int r = e >> 7, h = e & 127;
        const float* base = pfin + (((size_t)b * ND) * NJK + jk0 + r) * NH + h;
        float m = base[0];
#pragma unroll
        for (int d = 1; d < ND; d++)
            m = fmaxf(m, base[(size_t)d * NJK * NH]);
        sP[r][h] = m;
    }
    __syncthreads();

    int n = t * 2;
    float2 bv = *(const float2*)(b1 + n);
    float acc[8][2];
#pragma unroll
    for (int r = 0; r < 8; r++) { acc[r][0] = bv.x; acc[r][1] = bv.y; }

#pragma unroll 4
    for (int k = 0; k < NH; k++) {
        float2 w = *(const float2*)(W1p + (size_t)k * HID + n);
#pragma unroll
        for (int r = 0; r < 8; r++) {
            float x = sP[r][k];
            acc[r][0] = fmaf(x, w.x, acc[r][0]);
            acc[r][1] = fmaf(x, w.y, acc[r][1]);
        }
    }
#pragma unroll
    for (int r = 0; r < 8; r++)
        *(float2*)(g_C + ((size_t)b * NJK + jk0 + r) * HID + n) =
            make_float2(acc[r][0], acc[r][1]);
}

// ---------------------------------------------------------------------------
// Kernel T: g_W2h[n][k] = half(W2[k][n])
// ---------------------------------------------------------------------------
__global__ void k_w2h(const float* __restrict__ W2) {
    __shared__ float t[32][33];
    int n0 = blockIdx.x * 32, k0 = blockIdx.y * 32;
    int tx = threadIdx.x, ty = threadIdx.y;
#pragma unroll
    for (int r = ty; r < 32; r += 8)
        t[r][tx] = W2[(size_t)(k0 + r) * HID + n0 + tx];
    __syncthreads();
#pragma unroll
    for (int r = ty; r < 32; r += 8)
        g_W2h[(size_t)(n0 + r) * HID + k0 + tx] = __float2half(t[tx][r]);
}

// ---------------------------------------------------------------------------
// Kernel C: fp16 mma.sync, TILE_M=64, 256 threads, 2 CTAs/SM.
//   8 warps: wm = wid&1 (M 32-blocks), wn = wid>>1 (N 64-blocks of 256-slice)
// ---------------------------------------------------------------------------
__global__ __launch_bounds__(THREADS, 2)
void k_main(const float* __restrict__ b2, const float* __restrict__ W3,
            const float* __restrict__ b3, const float* __restrict__ psc,
            const float* __restrict__ pbi, float* __restrict__ out) {
    extern __shared__ char smem[];
    int*    coff = (int*)(smem + SM_COFF);
    float*  sA   = (float*)(smem + SM_SA);
    float2* bw   = (float2*)(smem + SM_BW);
    float*  vred = (float*)(smem + SM_VRED);

    const uint32_t sbase = smem_u32(smem);
    const int tid = threadIdx.x;
    const int lane = tid & 31;
    const int wid = tid >> 5;
    const int g = lane >> 2, tig = lane & 3;
    const int wm = wid & 1, wn = wid >> 1;
    const int b = blockIdx.z;
    const int i = blockIdx.y;
    const int jk0 = blockIdx.x * TILE_M;

    if (tid < TILE_M)
        coff[tid] = (b * NJK + jk0 + tid) * HID;
    {
        const float* ga = g_A + ((size_t)b * NNODE + i) * HID;
        for (int t = tid; t < HID; t += THREADS) sA[t] = ga[t];
        for (int n = tid; n < HID; n += THREADS) bw[n] = make_float2(b2[n], W3[n]);
    }
    __syncthreads();

    // ---- staging descriptors (2 C units + 4 B units per thread) ----
    const float* csrc[2];
    uint32_t adst[2];
#pragma unroll
    for (int q = 0; q < 2; q++) {
        int u = tid + q * THREADS;        // 512 C 16B-units
        int m = u >> 3, e = u & 7;
        csrc[q] = g_C + coff[m] + e * 4;
        adst[q] = (uint32_t)(m * (CST * 4) + e * 16);
    }
    int bn[4], bf[4];
    uint32_t bdst[4];
#pragma unroll
    for (int q = 0; q < 4; q++) {
        int u = tid + q * THREADS;        // 1024 B 16B-units
        bn[q] = u >> 2;
        bf[q] = u & 3;
        bdst[q] = (uint32_t)(SM_BOFF + bn[q] * (BSTW * 4) + bf[q] * 16);
    }
    uint32_t stg[NSTG];
#pragma unroll
    for (int s = 0; s < NSTG; s++) stg[s] = sbase + SM_ST0 + s * STG_SZ;

    // ---- transform indices: 64 rows x 4 k-octets ----
    const int tm = tid & 63;
    const int g8 = tid >> 6;              // 0..3

    // ---- ldmatrix constant addresses ----
    const uint32_t arow = sbase + SM_AH +
        (uint32_t)((wm * 32 + (lane & 15)) * AHB + ((lane >> 4) << 4));
    const uint32_t bq = (uint32_t)(SM_BOFF +
        (wn * 64 + ((lane >> 4) << 3) + (lane & 7)) * (BSTW * 4) +
        (((lane >> 3) & 1) << 4));

    float v[4] = {0.f, 0.f, 0.f, 0.f};

    for (int np = 0; np < NPASS; np++) {
        const int n0 = np * TILE_N;
        const __half* bsrc[4];
#pragma unroll
        for (int q = 0; q < 4; q++)
            bsrc[q] = g_W2h + (size_t)(n0 + bn[q]) * HID + bf[q] * 8;

        float acc[2][8][4];
#pragma unroll
        for (int mt = 0; mt < 2; mt++)
#pragma unroll
            for (int nt = 0; nt < 8; nt++)
#pragma unroll
                for (int j = 0; j < 4; j++) acc[mt][nt][j] = 0.f;

        // prologue: issue chunks 0,1; transform chunk 0 into Ah[0]
#pragma unroll
        for (int c = 0; c < 2; c++) {
            const int kc = c * KCH;
            const uint32_t st = stg[c];
#pragma unroll
            for (int q = 0; q < 2; q++) cp16(st + adst[q], csrc[q] + kc);
#pragma unroll
            for (int q = 0; q < 4; q++) cp16(st + bdst[q], bsrc[q] + kc);
            cp_commit();
        }
        cp_waitg<0>();
        __syncthreads();
        {
            const float* Cs = (const float*)(smem + SM_ST0);
            const float* cr = Cs + tm * CST + g8 * 8;
            float4 c0 = *(const float4*)(cr);
            float4 c1 = *(const float4*)(cr + 4);
            const float* ar = sA + g8 * 8;
            float4 a0 = *(const float4*)(ar);
            float4 a1 = *(const float4*)(ar + 4);
            uint4 o;
            o.x = h2pack(fmaxf(c0.x + a0.x, 0.f), fmaxf(c0.y + a0.y, 0.f));
            o.y = h2pack(fmaxf(c0.z + a0.z, 0.f), fmaxf(c0.w + a0.w, 0.f));
            o.z = h2pack(fmaxf(c1.x + a1.x, 0.f), fmaxf(c1.y + a1.y, 0.f));
            o.w = h2pack(fmaxf(c1.z + a1.z, 0.f), fmaxf(c1.w + a1.w, 0.f));
            *(uint4*)(smem + SM_AH + tm * AHB + g8 * 16) = o;
        }

        for (int c = 0; c < NCHUNKS; c++) {
            __syncthreads();   // Ah[c&1] visible; prior stage/Ah reads done

            if (c + 2 < NCHUNKS) {
                const int kc = (c + 2) * KCH;
                const uint32_t st = stg[(c + 2) % NSTG];
#pragma unroll
                for (int q = 0; q < 2; q++) cp16(st + adst[q], csrc[q] + kc);
#pragma unroll
                for (int q = 0; q < 4; q++) cp16(st + bdst[q], bsrc[q] + kc);
                cp_commit();
                cp_waitg<1>();      // chunk c+1 resident
            } else {
                cp_waitg<0>();
            }

            // ---- transform chunk c+1 into Ah[(c+1)&1] (overlaps MMA) ----
            if (c + 1 < NCHUNKS) {
                const float* Cs =
                    (const float*)(smem + SM_ST0 + ((c + 1) % NSTG) * STG_SZ);
                const float* cr = Cs + tm * CST + g8 * 8;
                float4 c0 = *(const float4*)(cr);
                float4 c1 = *(const float4*)(cr + 4);
                const float* ar = sA + (c + 1) * KCH + g8 * 8;
                float4 a0 = *(const float4*)(ar);
                float4 a1 = *(const float4*)(ar + 4);
                uint4 o;
                o.x = h2pack(fmaxf(c0.x + a0.x, 0.f), fmaxf(c0.y + a0.y, 0.f));
                o.y = h2pack(fmaxf(c0.z + a0.z, 0.f), fmaxf(c0.w + a0.w, 0.f));
                o.z = h2pack(fmaxf(c1.x + a1.x, 0.f), fmaxf(c1.y + a1.y, 0.f));
                o.w = h2pack(fmaxf(c1.z + a1.z, 0.f), fmaxf(c1.w + a1.w, 0.f));
                *(uint4*)(smem + SM_AH + ((c + 1) & 1) * AHBUF + tm * AHB + g8 * 16) = o;
            }

            // ---- MMA chunk c ----
            const uint32_t stgb = sbase + SM_ST0 + (c % NSTG) * STG_SZ;
            const uint32_t aro = arow + (c & 1) * AHBUF;
#pragma unroll
            for (int kst = 0; kst < 2; kst++) {
                uint32_t afr[2][4];
                ldmx4(afr[0], aro + kst * 32);
                ldmx4(afr[1], aro + kst * 32 + 16 * AHB);
#pragma unroll
                for (int p = 0; p < 4; p++) {
                    uint32_t bfr[4];
                    ldmx4(bfr, stgb + bq + p * (16 * BSTW * 4) + kst * 32);
                    mma_f16(acc[0][2 * p], afr[0], bfr[0], bfr[1]);
                    mma_f16(acc[1][2 * p], afr[1], bfr[0], bfr[1]);
                    mma_f16(acc[0][2 * p + 1], afr[0], bfr[2], bfr[3]);
                    mma_f16(acc[1][2 * p + 1], afr[1], bfr[2], bfr[3]);
                }
            }
        }
        __syncthreads();   // stage + Ah reuse safety across passes

        // epilogue accumulate: v += relu(acc + b2) * W3
#pragma unroll
        for (int mt = 0; mt < 2; mt++)
#pragma unroll
            for (int nt = 0; nt < 8; nt++)
#pragma unroll
                for (int j = 0; j < 4; j++) {
                    const int nl = wn * 64 + nt * 8 + tig * 2 + (j & 1);
                    float2 p = bw[n0 + nl];
                    v[mt * 2 + (j >> 1)] += fmaxf(acc[mt][nt][j] + p.x, 0.f) * p.y;
                }
    }

    // reduce over quad lanes; combine 4 wn groups via smem
#pragma unroll
    for (int r = 0; r < 4; r++) {
        v[r] += __shfl_xor_sync(0xffffffffu, v[r], 1);
        v[r] += __shfl_xor_sync(0xffffffffu, v[r], 2);
    }
    if (tig == 0) {
#pragma unroll
        for (int mt = 0; mt < 2; mt++)
#pragma unroll
            for (int half = 0; half < 2; half++)
                vred[wn * 64 + wm * 32 + mt * 16 + half * 8 + g] =
                    v[mt * 2 + half];
    }
    __syncthreads();

    if (tid < TILE_M) {
        float sum = vred[tid] + vred[64 + tid] + vred[128 + tid] + vred[192 + tid];
        float sc = __ldg(psc), bi2 = __ldg(pbi), b3v = __ldg(b3);
        float z = sc * (sum + b3v) + bi2;
        out[((size_t)b * NNODE + i) * NJK + jk0 + tid] = 1.f / (1.f + expf(-z));
    }
}

// ---------------------------------------------------------------------------
extern "C" void kernel_launch(void* const* d_in, const int* in_sizes, int n_in,
                              void* d_out, int out_size) {
    const float* node = (const float*)d_in[0];
    const float* pair = (const float*)d_in[1];
    const float* W1n  = (const float*)d_in[2];
    const float* W1p  = (const float*)d_in[3];
    const float* b1   = (const float*)d_in[4];
    const float* W2   = (const float*)d_in[5];
    const float* b2   = (const float*)d_in[6];
    const float* W3   = (const float*)d_in[7];
    const float* b3   = (const float*)d_in[8];
    const float* sc   = (const float*)d_in[9];
    const float* bi   = (const float*)d_in[10];
    float* out = (float*)d_out;

    cudaFuncSetAttribute(k_main, cudaFuncAttributeMaxDynamicSharedMemorySize,
                         SM_TOTAL);

    k_node<<<dim3(NB * NNODE, 4), NH>>>(node, W1n);
    k_pair<<<NB * NJK / 8, 256>>>(pair, W1p, b1);
    k_w2h<<<dim3(16, 16), dim3(32, 8)>>>(W2);

    dim3 grid(NJT, NNODE, NB);   // 25 x 40 x 2 = 2000 CTAs
    k_main<<<grid, THREADS, SM_TOTAL>>>(b2, W3, b3, sc, bi, out);
}

// round 12
// speedup vs baseline: 2.2050x; 2.2050x over previous
#include <cuda_runtime.h>
#include <cuda_fp16.h>
#include <cstdint>

#define NB 2
#define ND 8
#define NNODE 40
#define NH 128
#define HID 512
#define NJK (NNODE * NNODE)        // 1600
#define NJT 13                     // ceil(1600/128)
#define TILE_M 128
#define TILE_N 256
#define NPASS (HID / TILE_N)       // 2
#define KCH 64
#define NCHUNKS (HID / KCH)        // 8
#define THREADS 512

#define RSTB 144                   // row stride bytes (72 halfs) for C/B/Ah
#define AHBUF 18432                // one Ah buffer: 128*144

// -------- device scratch --------
__device__ __half g_Ah[NB * NNODE * HID];  // hn        [b][i][k]  half
__device__ __half g_Ch[NB * NJK * HID];    // hp + b1   [b][jk][k] half
__device__ __half g_W2h[HID * HID];        // W2^T      [n][k]     half

// -------- dynamic smem layout (bytes) --------
#define SM_COFF   0                        // 128 ints
#define SM_SA     512                      // 512 halfs (gA row)
#define SM_BW     1536                     // 512 float2 (b2, W3)
#define SM_VRED   5632                     // 512 f32
#define SM_AH     7680                     // 2 x 18432
#define SM_ST0    45056                    // stages (1024-aligned)
#define SM_BOFF   18432                    // B offset within stage (C = 128*144)
#define STG_SZ    55296                    // C 18432 + B 36864
#define SM_TOTAL  (SM_ST0 + 2 * STG_SZ)   // 155648

__device__ __forceinline__ uint32_t smem_u32(const void* p) {
    uint32_t a;
    asm("{ .reg .u64 t; cvta.to.shared.u64 t, %1; cvt.u32.u64 %0, t; }" : "=r"(a) : "l"(p));
    return a;
}
__device__ __forceinline__ uint32_t h2pack(float lo, float hi) {
    uint32_t r;
    asm("cvt.rn.f16x2.f32 %0, %1, %2;" : "=r"(r) : "f"(hi), "f"(lo));
    return r;
}
__device__ __forceinline__ uint32_t hadd_relu2(uint32_t c, uint32_t a) {
    __half2 x = __hadd2(*(__half2*)&c, *(__half2*)&a);
    x = __hmax2(x, __float2half2_rn(0.f));
    return *(uint32_t*)&x;
}
__device__ __forceinline__ void cp16(uint32_t dst, const void* src) {
    asm volatile("cp.async.cg.shared.global [%0], [%1], 16;" :: "r"(dst), "l"(src) : "memory");
}
__device__ __forceinline__ void cp_commit() {
    asm volatile("cp.async.commit_group;" ::: "memory");
}
template <int N>
__device__ __forceinline__ void cp_waitg() {
    asm volatile("cp.async.wait_group %0;" :: "n"(N) : "memory");
}
__device__ __forceinline__ void ldmx4(uint32_t* r, uint32_t addr) {
    asm volatile("ldmatrix.sync.aligned.m8n8.x4.shared.b16 {%0,%1,%2,%3}, [%4];"
                 : "=r"(r[0]), "=r"(r[1]), "=r"(r[2]), "=r"(r[3]) : "r"(addr));
}
__device__ __forceinline__ void mma_f16(float* d, const uint32_t* a,
                                        uint32_t b0, uint32_t b1) {
    asm volatile(
        "mma.sync.aligned.m16n8k16.row.col.f32.f16.f16.f32 "
        "{%0,%1,%2,%3}, {%4,%5,%6,%7}, {%8,%9}, {%0,%1,%2,%3};"
        : "+f"(d[0]), "+f"(d[1]), "+f"(d[2]), "+f"(d[3])
        : "r"(a[0]), "r"(a[1]), "r"(a[2]), "r"(a[3]), "r"(b0), "r"(b1));
}

// ---------------------------------------------------------------------------
// Kernel A: nf = max_d(node_feature); g_Ah[b][i][:] = half(nf @ W1n)
// ---------------------------------------------------------------------------
__global__ void k_node(const float* __restrict__ nfin,
                       const float* __restrict__ W1n) {
    __shared__ float s[NH];
    __shared__ float4 red[4][32];
    int bi = blockIdx.x, nq = blockIdx.y;
    int b = bi / NNODE, i = bi % NNODE;
    int t = threadIdx.x;

    const float* base = nfin + (((size_t)b * ND) * NNODE + i) * NH + t;
    float m = base[0];
#pragma unroll
    for (int d = 1; d < ND; d++)
        m = fmaxf(m, base[(size_t)d * NNODE * NH]);
    s[t] = m;
    __syncthreads();

    int hq = t >> 5, c = t & 31;
    int n = nq * 128 + c * 4;
    float a0 = 0.f, a1 = 0.f, a2 = 0.f, a3 = 0.f;
#pragma unroll 8
    for (int h = hq * 32; h < hq * 32 + 32; h++) {
        float4 wv = *(const float4*)(W1n + (size_t)h * HID + n);
        float x = s[h];
        a0 = fmaf(x, wv.x, a0);
        a1 = fmaf(x, wv.y, a1);
        a2 = fmaf(x, wv.z, a2);
        a3 = fmaf(x, wv.w, a3);
    }
    red[hq][c] = make_float4(a0, a1, a2, a3);
    __syncthreads();
    if (hq == 0) {
        float4 r0 = red[0][c], r1 = red[1][c], r2 = red[2][c], r3 = red[3][c];
        uint2 o;
        o.x = h2pack(r0.x + r1.x + r2.x + r3.x, r0.y + r1.y + r2.y + r3.y);
        o.y = h2pack(r0.z + r1.z + r2.z + r3.z, r0.w + r1.w + r2.w + r3.w);
        *(uint2*)(g_Ah + (size_t)bi * HID + n) = o;
    }
}

// ---------------------------------------------------------------------------
// Kernel B: pf = max_d(pairwise_feature); g_Ch[b][jk][:] = half(pf @ W1p + b1)
// ---------------------------------------------------------------------------
__global__ void k_pair(const float* __restrict__ pfin,
                       const float* __restrict__ W1p,
                       const float* __restrict__ b1) {
    __shared__ float sP[8][NH];
    int row0 = blockIdx.x * 8;
    int b = row0 / NJK, jk0 = row0 % NJK;
    int t = threadIdx.x;

    for (int e = t; e < 8 * NH; e += 256) {
        int r = e >> 7, h = e & 127;
        const float* base = pfin + (((size_t)b * ND) * NJK + jk0 + r) * NH + h;
        float m = base[0];
#pragma unroll
        for (int d = 1; d < ND; d++)
            m = fmaxf(m, base[(size_t)d * NJK * NH]);
        sP[r][h] = m;
    }
    __syncthreads();

    int n = t * 2;
    float2 bv = *(const float2*)(b1 + n);
    float acc[8][2];
#pragma unroll
    for (int r = 0; r < 8; r++) { acc[r][0] = bv.x; acc[r][1] = bv.y; }

#pragma unroll 4
    for (int k = 0; k < NH; k++) {
        float2 w = *(const float2*)(W1p + (size_t)k * HID + n);
#pragma unroll
        for (int r = 0; r < 8; r++) {
            float x = sP[r][k];
            acc[r][0] = fmaf(x, w.x, acc[r][0]);
            acc[r][1] = fmaf(x, w.y, acc[r][1]);
        }
    }
#pragma unroll
    for (int r = 0; r < 8; r++)
        *(uint32_t*)(g_Ch + ((size_t)b * NJK + jk0 + r) * HID + n) =
            h2pack(acc[r][0], acc[r][1]);
}

// ---------------------------------------------------------------------------
// Kernel T: g_W2h[n][k] = half(W2[k][n])
// ---------------------------------------------------------------------------
__global__ void k_w2h(const float* __restrict__ W2) {
    __shared__ float t[32][33];
    int n0 = blockIdx.x * 32, k0 = blockIdx.y * 32;
    int tx = threadIdx.x, ty = threadIdx.y;
#pragma unroll
    for (int r = ty; r < 32; r += 8)
        t[r][tx] = W2[(size_t)(k0 + r) * HID + n0 + tx];
    __syncthreads();
#pragma unroll
    for (int r = ty; r < 32; r += 8)
        g_W2h[(size_t)(n0 + r) * HID + k0 + tx] = __float2half(t[tx][r]);
}

// ---------------------------------------------------------------------------
// Kernel C: fp16 mma.sync, KCH=64, 2-stage cp.async, half transform,
// one barrier per chunk. 16 warps: wm=wid&3, wn=wid>>2.
// ---------------------------------------------------------------------------
__global__ __launch_bounds__(THREADS, 1)
void k_main(const float* __restrict__ b2, const float* __restrict__ W3,
            const float* __restrict__ b3, const float* __restrict__ psc,
            const float* __restrict__ pbi, float* __restrict__ out) {
    extern __shared__ char smem[];
    int*    coff = (int*)(smem + SM_COFF);
    float2* bw   = (float2*)(smem + SM_BW);
    float*  vred = (float*)(smem + SM_VRED);

    const uint32_t sbase = smem_u32(smem);
    const int tid = threadIdx.x;
    const int lane = tid & 31;
    const int wid = tid >> 5;
    const int g = lane >> 2, tig = lane & 3;
    const int wm = wid & 3, wn = wid >> 2;
    const int b = blockIdx.z;
    const int i = blockIdx.y;
    const int jk0 = blockIdx.x * TILE_M;

    if (tid < TILE_M) {
        int jk = jk0 + tid;
        if (jk > NJK - 1) jk = NJK - 1;
        coff[tid] = (b * NJK + jk) * HID;
    }
    {
        const __half* ga = g_Ah + ((size_t)b * NNODE + i) * HID;
        ((__half*)(smem + SM_SA))[tid] = ga[tid];
        for (int n = tid; n < HID; n += THREADS) bw[n] = make_float2(b2[n], W3[n]);
    }
    __syncthreads();

    // ---- staging: C 1024 units (2/thr), B 2048 units (4/thr). Self-mapped C.
    const __half* csrc[2];
    uint32_t adst[2];
    int crow[2], ce[2];
#pragma unroll
    for (int q = 0; q < 2; q++) {
        int u = tid + q * THREADS;
        crow[q] = u >> 3;
        ce[q] = u & 7;
        csrc[q] = g_Ch + coff[crow[q]] + ce[q] * 8;
        adst[q] = (uint32_t)(crow[q] * RSTB + ce[q] * 16);
    }
    int bn[4], bf[4];
    uint32_t bdst[4];
#pragma unroll
    for (int q = 0; q < 4; q++) {
        int u = tid + q * THREADS;
        bn[q] = u >> 3;
        bf[q] = u & 7;
        bdst[q] = (uint32_t)(SM_BOFF + bn[q] * RSTB + bf[q] * 16);
    }
    uint32_t stg[2] = {sbase + SM_ST0, sbase + SM_ST0 + STG_SZ};

    // ---- ldmatrix constant addresses ----
    const uint32_t arow = sbase + SM_AH +
        (uint32_t)((wm * 32 + (lane & 15)) * RSTB + ((lane >> 4) << 4));
    const uint32_t bq = (uint32_t)(SM_BOFF +
        (wn * 64 + ((lane >> 4) << 3) + (lane & 7)) * RSTB +
        (((lane >> 3) & 1) << 4));

    float v[4] = {0.f, 0.f, 0.f, 0.f};

    for (int np = 0; np < NPASS; np++) {
        const int n0 = np * TILE_N;
        const __half* bsrc[4];
#pragma unroll
        for (int q = 0; q < 4; q++)
            bsrc[q] = g_W2h + (size_t)(n0 + bn[q]) * HID + bf[q] * 8;

        float acc[2][8][4];
#pragma unroll
        for (int mt = 0; mt < 2; mt++)
#pragma unroll
            for (int nt = 0; nt < 8; nt++)
#pragma unroll
                for (int j = 0; j < 4; j++) acc[mt][nt][j] = 0.f;

        // ---- prologue: load + transform chunk 0 ----
#pragma unroll
        for (int q = 0; q < 2; q++) cp16(stg[0] + adst[q], csrc[q]);
#pragma unroll
        for (int q = 0; q < 4; q++) cp16(stg[0] + bdst[q], bsrc[q]);
        cp_commit();
        cp_waitg<0>();
        {
            const char* Cs = smem + SM_ST0;
            const char* sab = smem + SM_SA;
            char* Ahb = smem + SM_AH;
#pragma unroll
            for (int q = 0; q < 2; q++) {
                uint4 cv = *(const uint4*)(Cs + adst[q]);
                uint4 av = *(const uint4*)(sab + ce[q] * 16);
                uint4 o;
                o.x = hadd_relu2(cv.x, av.x);
                o.y = hadd_relu2(cv.y, av.y);
                o.z = hadd_relu2(cv.z, av.z);
                o.w = hadd_relu2(cv.w, av.w);
                *(uint4*)(Ahb + adst[q]) = o;
            }
        }

        for (int c = 0; c < NCHUNKS; c++) {
            __syncthreads();   // publish Ah[c&1] + B stage c&1

            if (c + 1 < NCHUNKS) {
                const int kc = (c + 1) * KCH;
                const uint32_t st = stg[(c + 1) & 1];
#pragma unroll
                for (int q = 0; q < 2; q++) cp16(st + adst[q], csrc[q] + kc);
#pragma unroll
                for (int q = 0; q < 4; q++) cp16(st + bdst[q], bsrc[q] + kc);
                cp_commit();
            }

            // ---- MMA chunk c ----
            {
                const uint32_t stgb = stg[c & 1];
                const uint32_t aro = arow + (c & 1) * AHBUF;
#pragma unroll
                for (int kst = 0; kst < 4; kst++) {
                    uint32_t afr[2][4];
                    ldmx4(afr[0], aro + kst * 32);
                    ldmx4(afr[1], aro + kst * 32 + 16 * RSTB);
#pragma unroll
                    for (int p = 0; p < 4; p++) {
                        uint32_t bfr[4];
                        ldmx4(bfr, stgb + bq + p * (16 * RSTB) + kst * 32);
                        mma_f16(acc[0][2 * p], afr[0], bfr[0], bfr[1]);
                        mma_f16(acc[1][2 * p], afr[1], bfr[0], bfr[1]);
                        mma_f16(acc[0][2 * p + 1], afr[0], bfr[2], bfr[3]);
                        mma_f16(acc[1][2 * p + 1], afr[1], bfr[2], bfr[3]);
                    }
                }
            }

            // ---- wait + transform chunk c+1 (self-mapped; no barrier) ----
            if (c + 1 < NCHUNKS) {
                cp_waitg<0>();
                const char* Cs = smem + SM_ST0 + ((c + 1) & 1) * STG_SZ;
                const char* sab = smem + SM_SA + (c + 1) * (KCH * 2);
                char* Ahb = smem + SM_AH + ((c + 1) & 1) * AHBUF;
#pragma unroll
                for (int q = 0; q < 2; q++) {
                    uint4 cv = *(const uint4*)(Cs + adst[q]);
                    uint4 av = *(const uint4*)(sab + ce[q] * 16);
                    uint4 o;
                    o.x = hadd_relu2(cv.x, av.x);
                    o.y = hadd_relu2(cv.y, av.y);
                    o.z = hadd_relu2(cv.z, av.z);
                    o.w = hadd_relu2(cv.w, av.w);
                    *(uint4*)(Ahb + adst[q]) = o;
                }
            }
        }
        __syncthreads();   // safety across passes

        // ---- epilogue accumulate: v += relu(acc + b2) * W3 ----
#pragma unroll
        for (int mt = 0; mt < 2; mt++)
#pragma unroll
            for (int nt = 0; nt < 8; nt++)
#pragma unroll
                for (int j = 0; j < 4; j++) {
                    const int nl = wn * 64 + nt * 8 + tig * 2 + (j & 1);
                    float2 p = bw[n0 + nl];
                    v[mt * 2 + (j >> 1)] += fmaxf(acc[mt][nt][j] + p.x, 0.f) * p.y;
                }
    }

    // reduce over quad lanes; combine 4 wn groups via smem
#pragma unroll
    for (int r = 0; r < 4; r++) {
        v[r] += __shfl_xor_sync(0xffffffffu, v[r], 1);
        v[r] += __shfl_xor_sync(0xffffffffu, v[r], 2);
    }
    if (tig == 0) {
#pragma unroll
        for (int mt = 0; mt < 2; mt++)
#pragma unroll
            for (int half = 0; half < 2; half++)
                vred[wn * 128 + wm * 32 + mt * 16 + half * 8 + g] =
                    v[mt * 2 + half];
    }
    __syncthreads();

    if (tid < TILE_M && jk0 + tid < NJK) {
        float sum = vred[tid] + vred[128 + tid] + vred[256 + tid] + vred[384 + tid];
        float sc = __ldg(psc), bi2 = __ldg(pbi), b3v = __ldg(b3);
        float z = sc * (sum + b3v) + bi2;
        out[((size_t)b * NNODE + i) * NJK + jk0 + tid] = 1.f / (1.f + expf(-z));
    }
}

// ---------------------------------------------------------------------------
extern "C" void kernel_launch(void* const* d_in, const int* in_sizes, int n_in,
                              void* d_out, int out_size) {
    const float* node = (const float*)d_in[0];
    const float* pair = (const float*)d_in[1];
    const float* W1n  = (const float*)d_in[2];
    const float* W1p  = (const float*)d_in[3];
    const float* b1   = (const float*)d_in[4];
    const float* W2   = (const float*)d_in[5];
    const float* b2   = (const float*)d_in[6];
    const float* W3   = (const float*)d_in[7];
    const float* b3   = (const float*)d_in[8];
    const float* sc   = (const float*)d_in[9];
    const float* bi   = (const float*)d_in[10];
    float* out = (float*)d_out;

    cudaFuncSetAttribute(k_main, cudaFuncAttributeMaxDynamicSharedMemorySize,
                         SM_TOTAL);

    k_node<<<dim3(NB * NNODE, 4), NH>>>(node, W1n);
    k_pair<<<NB * NJK / 8, 256>>>(pair, W1p, b1);
    k_w2h<<<dim3(16, 16), dim3(32, 8)>>>(W2);

    dim3 grid(NJT, NNODE, NB);   // 13 x 40 x 2 = 1040 CTAs
    k_main<<<grid, THREADS, SM_TOTAL>>>(b2, W3, b3, sc, bi, out);
}

// round 15
// speedup vs baseline: 2.2890x; 1.0381x over previous
#include <cuda_runtime.h>
#include <cuda_fp16.h>
#include <cstdint>

#define NB 2
#define ND 8
#define NNODE 40
#define NH 128
#define HID 512
#define NJK (NNODE * NNODE)        // 1600
#define NJT 13                     // ceil(1600/128)
#define TILE_M 128
#define TILE_N 256
#define NPASS (HID / TILE_N)       // 2
#define KCH 64
#define NCHUNKS (HID / KCH)        // 8
#define NSTG 3
#define THREADS 512

#define RSTB 144                   // row stride bytes (72 halfs) for C/B/Ah
#define AHBUF 18432                // one Ah buffer: 128*144

// -------- device scratch --------
__device__ __half g_Ah[NB * NNODE * HID];  // hn        [b][i][k]  half
__device__ __half g_Ch[NB * NJK * HID];    // hp + b1   [b][jk][k] half
__device__ __half g_W2h[HID * HID];        // W2^T      [n][k]     half

// -------- dynamic smem layout (bytes) --------
#define SM_COFF   0                        // 128 ints
#define SM_SA     512                      // 512 halfs (gA row)
#define SM_BW     1536                     // 512 float2 (b2, W3)
#define SM_VRED   5632                     // 512 f32
#define SM_AH     7680                     // 2 x 18432
#define SM_ST0    45056                    // stages (1024-aligned)
#define SM_BOFF   18432                    // B offset within stage (C = 128*144)
#define STG_SZ    55296                    // C 18432 + B 36864
#define SM_TOTAL  (SM_ST0 + NSTG * STG_SZ) // 210944 (<= 227KB, 1 CTA/SM)

__device__ __forceinline__ uint32_t smem_u32(const void* p) {
    uint32_t a;
    asm("{ .reg .u64 t; cvta.to.shared.u64 t, %1; cvt.u32.u64 %0, t; }" : "=r"(a) : "l"(p));
    return a;
}
__device__ __forceinline__ uint32_t h2pack(float lo, float hi) {
    uint32_t r;
    asm("cvt.rn.f16x2.f32 %0, %1, %2;" : "=r"(r) : "f"(hi), "f"(lo));
    return r;
}
__device__ __forceinline__ uint32_t hadd_relu2(uint32_t c, uint32_t a) {
    __half2 x = __hadd2(*(__half2*)&c, *(__half2*)&a);
    x = __hmax2(x, __float2half2_rn(0.f));
    return *(uint32_t*)&x;
}
__device__ __forceinline__ void cp16(uint32_t dst, const void* src) {
    asm volatile("cp.async.cg.shared.global [%0], [%1], 16;" :: "r"(dst), "l"(src) : "memory");
}
__device__ __forceinline__ void cp_commit() {
    asm volatile("cp.async.commit_group;" ::: "memory");
}
template <int N>
__device__ __forceinline__ void cp_waitg() {
    asm volatile("cp.async.wait_group %0;" :: "n"(N) : "memory");
}
__device__ __forceinline__ void ldmx4(uint32_t* r, uint32_t addr) {
    asm volatile("ldmatrix.sync.aligned.m8n8.x4.shared.b16 {%0,%1,%2,%3}, [%4];"
                 : "=r"(r[0]), "=r"(r[1]), "=r"(r[2]), "=r"(r[3]) : "r"(addr));
}
__device__ __forceinline__ void mma_f16(float* d, const uint32_t* a,
                                        uint32_t b0, uint32_t b1) {
    asm volatile(
        "mma.sync.aligned.m16n8k16.row.col.f32.f16.f16.f32 "
        "{%0,%1,%2,%3}, {%4,%5,%6,%7}, {%8,%9}, {%0,%1,%2,%3};"
        : "+f"(d[0]), "+f"(d[1]), "+f"(d[2]), "+f"(d[3])
        : "r"(a[0]), "r"(a[1]), "r"(a[2]), "r"(a[3]), "r"(b0), "r"(b1));
}

// ---------------------------------------------------------------------------
// Kernel PRE (merged): blocks [0,400) pair, [400,656) w2t, [656,736) node.
// 256 threads each.
// ---------------------------------------------------------------------------
#define NPAIR_BLK (NB * NJK / 8)    // 400
#define NW2T_BLK  256

__global__ void k_pre(const float* __restrict__ nfin,
                      const float* __restrict__ pfin,
                      const float* __restrict__ W1n,
                      const float* __restrict__ W1p,
                      const float* __restrict__ b1,
                      const float* __restrict__ W2) {
    __shared__ float sh[1088];      // pair: 8x128, w2t: 32x33, node: 128
    int bid = blockIdx.x;
    int t = threadIdx.x;

    if (bid < NPAIR_BLK) {
        // ---- pair: pf = max_d; g_Ch = half(pf @ W1p + b1) ----
        float (*sP)[NH] = (float(*)[NH])sh;
        int row0 = bid * 8;
        int b = row0 / NJK, jk0 = row0 % NJK;
        for (int e = t; e < 8 * NH; e += 256) {
            int r = e >> 7, h = e & 127;
            const float* base = pfin + (((size_t)b * ND) * NJK + jk0 + r) * NH + h;
            float m = base[0];
#pragma unroll
            for (int d = 1; d < ND; d++)
                m = fmaxf(m, base[(size_t)d * NJK * NH]);
            sP[r][h] = m;
        }
        __syncthreads();
        int n = t * 2;
        float2 bv = *(const float2*)(b1 + n);
        float acc[8][2];
#pragma unroll
        for (int r = 0; r < 8; r++) { acc[r][0] = bv.x; acc[r][1] = bv.y; }
#pragma unroll 4
        for (int k = 0; k < NH; k++) {
            float2 w = *(const float2*)(W1p + (size_t)k * HID + n);
#pragma unroll
            for (int r = 0; r < 8; r++) {
                float x = sP[r][k];
                acc[r][0] = fmaf(x, w.x, acc[r][0]);
                acc[r][1] = fmaf(x, w.y, acc[r][1]);
            }
        }
#pragma unroll
        for (int r = 0; r < 8; r++)
            *(uint32_t*)(g_Ch + ((size_t)b * NJK + jk0 + r) * HID + n) =
                h2pack(acc[r][0], acc[r][1]);
    } else if (bid < NPAIR_BLK + NW2T_BLK) {
        // ---- w2t: g_W2h[n][k] = half(W2[k][n]) ----
        int q = bid - NPAIR_BLK;
        int n0 = (q & 15) * 32, k0 = (q >> 4) * 32;
        int tx = t & 31, ty = t >> 5;   // 32 x 8
        float (*tt)[33] = (float(*)[33])sh;
#pragma unroll
        for (int r = ty; r < 32; r += 8)
            tt[r][tx] = W2[(size_t)(k0 + r) * HID + n0 + tx];
        __syncthreads();
#pragma unroll
        for (int r = ty; r < 32; r += 8)
            g_W2h[(size_t)(n0 + r) * HID + k0 + tx] = __float2half(tt[tx][r]);
    } else {
        // ---- node: nf = max_d; g_Ah = half(nf @ W1n) ----
        int bi = bid - NPAIR_BLK - NW2T_BLK;  // 0..79
        int b = bi / NNODE, i = bi % NNODE;
        if (t < NH) {
            const float* base = nfin + (((size_t)b * ND) * NNODE + i) * NH + t;
            float m = base[0];
#pragma unroll
            for (int d = 1; d < ND; d++)
                m = fmaxf(m, base[(size_t)d * NNODE * NH]);
            sh[t] = m;
        }
        __syncthreads();
        int n = t * 2;
        float a0 = 0.f, a1 = 0.f;
#pragma unroll 8
        for (int h = 0; h < NH; h++) {
            float2 w = *(const float2*)(W1n + (size_t)h * HID + n);
            float x = sh[h];
            a0 = fmaf(x, w.x, a0);
            a1 = fmaf(x, w.y, a1);
        }
        *(uint32_t*)(g_Ah + (size_t)bi * HID + n) = h2pack(a0, a1);
    }
}

// ---------------------------------------------------------------------------
// Kernel C: fp16 mma.sync, KCH=64, 3-stage cp.async, transform hidden
// mid-MMA, one barrier per chunk. 16 warps: wm=wid&3, wn=wid>>2.
// ---------------------------------------------------------------------------
__global__ __launch_bounds__(THREADS, 1)
void k_main(const float* __restrict__ b2, const float* __restrict__ W3,
            const float* __restrict__ b3, const float* __restrict__ psc,
            const float* __restrict__ pbi, float* __restrict__ out) {
    extern __shared__ char smem[];
    int*    coff = (int*)(smem + SM_COFF);
    float2* bw   = (float2*)(smem + SM_BW);
    float*  vred = (float*)(smem + SM_VRED);

    const uint32_t sbase = smem_u32(smem);
    const int tid = threadIdx.x;
    const int lane = tid & 31;
    const int wid = tid >> 5;
    const int g = lane >> 2, tig = lane & 3;
    const int wm = wid & 3, wn = wid >> 2;
    const int b = blockIdx.z;
    const int i = blockIdx.y;
    const int jk0 = blockIdx.x * TILE_M;

    if (tid < TILE_M) {
        int jk = jk0 + tid;
        if (jk > NJK - 1) jk = NJK - 1;
        coff[tid] = (b * NJK + jk) * HID;
    }
    {
        const __half* ga = g_Ah + ((size_t)b * NNODE + i) * HID;
        ((__half*)(smem + SM_SA))[tid] = ga[tid];
        for (int n = tid; n < HID; n += THREADS) bw[n] = make_float2(b2[n], W3[n]);
    }
    __syncthreads();

    // ---- staging: C 1024 units (2/thr), B 2048 units (4/thr). Self-mapped C.
    const __half* csrc[2];
    uint32_t adst[2];
    int ce[2];
#pragma unroll
    for (int q = 0; q < 2; q++) {
        int u = tid + q * THREADS;
        int crow = u >> 3;
        ce[q] = u & 7;
        csrc[q] = g_Ch + coff[crow] + ce[q] * 8;
        adst[q] = (uint32_t)(crow * RSTB + ce[q] * 16);
    }
    int bn[4], bf[4];
    uint32_t bdst[4];
#pragma unroll
    for (int q = 0; q < 4; q++) {
        int u = tid + q * THREADS;
        bn[q] = u >> 3;
        bf[q] = u & 7;
        bdst[q] = (uint32_t)(SM_BOFF + bn[q] * RSTB + bf[q] * 16);
    }
    uint32_t stg[NSTG];
#pragma unroll
    for (int s = 0; s < NSTG; s++) stg[s] = sbase + SM_ST0 + s * STG_SZ;

    // ---- ldmatrix constant addresses ----
    const uint32_t arow = sbase + SM_AH +
        (uint32_t)((wm * 32 + (lane & 15)) * RSTB + ((lane >> 4) << 4));
    const uint32_t bq = (uint32_t)(SM_BOFF +
        (wn * 64 + ((lane >> 4) << 3) + (lane & 7)) * RSTB +
        (((lane >> 3) & 1) << 4));

#define CP_ISSUE(cc, st) do {                                            \
        const int kc_ = (cc) * KCH;                                      \
        _Pragma("unroll")                                                \
        for (int q = 0; q < 2; q++) cp16((st) + adst[q], csrc[q] + kc_); \
        _Pragma("unroll")                                                \
        for (int q = 0; q < 4; q++) cp16((st) + bdst[q], bsrc[q] + kc_); \
        cp_commit();                                                     \
    } while (0)

#define TRANSFORM(cc) do {                                               \
        const char* Cs_ = smem + SM_ST0 + ((cc) % NSTG) * STG_SZ;        \
        const char* sab_ = smem + SM_SA + (cc) * (KCH * 2);              \
        char* Ahb_ = smem + SM_AH + ((cc) & 1) * AHBUF;                  \
        _Pragma("unroll")                                                \
        for (int q = 0; q < 2; q++) {                                    \
            uint4 cv = *(const uint4*)(Cs_ + adst[q]);                   \
            uint4 av = *(const uint4*)(sab_ + ce[q] * 16);               \
            uint4 o;                                                     \
            o.x = hadd_relu2(cv.x, av.x);                                \
            o.y = hadd_relu2(cv.y, av.y);                                \
            o.z = hadd_relu2(cv.z, av.z);                                \
            o.w = hadd_relu2(cv.w, av.w);                                \
            *(uint4*)(Ahb_ + adst[q]) = o;                               \
        }                                                                \
    } while (0)

#define MMA_KST(kst) do {                                                \
        uint32_t afr0[4], afr1[4];                                       \
        ldmx4(afr0, aro + (kst) * 32);                                   \
        ldmx4(afr1, aro + (kst) * 32 + 16 * RSTB);                       \
        _Pragma("unroll")                                                \
        for (int p = 0; p < 4; p++) {                                    \
            uint32_t bfr[4];                                             \
            ldmx4(bfr, stgb + bq + p * (16 * RSTB) + (kst) * 32);        \
            mma_f16(acc[0][2 * p], afr0, bfr[0], bfr[1]);                \
            mma_f16(acc[1][2 * p], afr1, bfr[0], bfr[1]);                \
            mma_f16(acc[0][2 * p + 1], afr0, bfr[2], bfr[3]);            \
            mma_f16(acc[1][2 * p + 1], afr1, bfr[2], bfr[3]);            \
        }                                                                \
    } while (0)

    float v[4] = {0.f, 0.f, 0.f, 0.f};

    for (int np = 0; np < NPASS; np++) {
        const int n0 = np * TILE_N;
        const __half* bsrc[4];
#pragma unroll
        for (int q = 0; q < 4; q++)
            bsrc[q] = g_W2h + (size_t)(n0 + bn[q]) * HID + bf[q] * 8;

        float acc[2][8][4];
#pragma unroll
        for (int mt = 0; mt < 2; mt++)
#pragma unroll
            for (int nt = 0; nt < 8; nt++)
#pragma unroll
                for (int j = 0; j < 4; j++) acc[mt][nt][j] = 0.f;

        // ---- prologue: issue chunks 0,1; transform chunk 0 ----
        CP_ISSUE(0, stg[0]);
        CP_ISSUE(1, stg[1]);
        cp_waitg<1>();          // chunk 0 resident (own writes, self-mapped)
        TRANSFORM(0);

        for (int c = 0; c < NCHUNKS; c++) {
            __syncthreads();    // publish Ah[c&1]; all prior stage reads done

            if (c + 2 < NCHUNKS) CP_ISSUE(c + 2, stg[(c + 2) % NSTG]);

            const uint32_t stgb = stg[c % NSTG];
            const uint32_t aro = arow + (c & 1) * AHBUF;

            MMA_KST(0);
            MMA_KST(1);

            // transform chunk c+1 in the shadow of kst 2,3 MMAs
            if (c + 1 < NCHUNKS) {
                if (c + 2 < NCHUNKS) cp_waitg<1>(); else cp_waitg<0>();
                TRANSFORM(c + 1);
            }

            MMA_KST(2);
            MMA_KST(3);
        }
        __syncthreads();        // safety across passes

        // ---- epilogue accumulate: v += relu(acc + b2) * W3 ----
#pragma unroll
        for (int mt = 0; mt < 2; mt++)
#pragma unroll
            for (int nt = 0; nt < 8; nt++)
#pragma unroll
                for (int j = 0; j < 4; j++) {
                    const int nl = wn * 64 + nt * 8 + tig * 2 + (j & 1);
                    float2 p = bw[n0 + nl];
                    v[mt * 2 + (j >> 1)] += fmaxf(acc[mt][nt][j] + p.x, 0.f) * p.y;
                }
    }

    // reduce over quad lanes; combine 4 wn groups via smem
#pragma unroll
    for (int r = 0; r < 4; r++) {
        v[r] += __shfl_xor_sync(0xffffffffu, v[r], 1);
        v[r] += __shfl_xor_sync(0xffffffffu, v[r], 2);
    }
    if (tig == 0) {
#pragma unroll
        for (int mt = 0; mt < 2; mt++)
#pragma unroll
            for (int half = 0; half < 2; half++)
                vred[wn * 128 + wm * 32 + mt * 16 + half * 8 + g] =
                    v[mt * 2 + half];
    }
    __syncthreads();

    if (tid < TILE_M && jk0 + tid < NJK) {
        float sum = vred[tid] + vred[128 + tid] + vred[256 + tid] + vred[384 + tid];
        float sc = __ldg(psc), bi2 = __ldg(pbi), b3v = __ldg(b3);
        float z = sc * (sum + b3v) + bi2;
        out[((size_t)b * NNODE + i) * NJK + jk0 + tid] = 1.f / (1.f + expf(-z));
    }
}

// ---------------------------------------------------------------------------
extern "C" void kernel_launch(void* const* d_in, const int* in_sizes, int n_in,
                              void* d_out, int out_size) {
    const float* node = (const float*)d_in[0];
    const float* pair = (const float*)d_in[1];
    const float* W1n  = (const float*)d_in[2];
    const float* W1p  = (const float*)d_in[3];
    const float* b1   = (const float*)d_in[4];
    const float* W2   = (const float*)d_in[5];
    const float* b2   = (const float*)d_in[6];
    const float* W3   = (const float*)d_in[7];
    const float* b3   = (const float*)d_in[8];
    const float* sc   = (const float*)d_in[9];
    const float* bi   = (const float*)d_in[10];
    float* out = (float*)d_out;

    cudaFuncSetAttribute(k_main, cudaFuncAttributeMaxDynamicSharedMemorySize,
                         SM_TOTAL);

    k_pre<<<NPAIR_BLK + NW2T_BLK + 80, 256>>>(node, pair, W1n, W1p, b1, W2);

    dim3 grid(NJT, NNODE, NB);   // 13 x 40 x 2 = 1040 CTAs
    k_main<<<grid, THREADS, SM_TOTAL>>>(b2, W3, b3, sc, bi, out);
}